// round 5
// baseline (speedup 1.0000x reference)
#include <cuda_runtime.h>
#include <math.h>

#define NB 16
#define NF 48
#define NM 51
#define HH 256
#define WW 256
#define LUTS 3200          // float2 slots (value, slope)
#define NPIX (NB*HH*WW)

// scratch (no allocations allowed)
__device__ float  g_wn[NF*49];
__device__ float2 g_lut2[NF*LUTS];
__device__ float  g_sums[NB];
__device__ float  g_r[NPIX];

typedef unsigned long long u64;

__device__ __forceinline__ u64 ffma2(u64 a, u64 b, u64 c) {
    u64 d;
    asm("fma.rn.f32x2 %0, %1, %2, %3;" : "=l"(d) : "l"(a), "l"(b), "l"(c));
    return d;
}
__device__ __forceinline__ u64 splat2(float x) {
    u64 r;
    asm("mov.b64 %0, {%1, %1};" : "=l"(r) : "f"(x));
    return r;
}
__device__ __forceinline__ float2 unpack2(u64 v) {
    float2 f;
    asm("mov.b64 {%0, %1}, %2;" : "=f"(f.x), "=f"(f.y) : "l"(v));
    return f;
}

// ---------------------------------------------------------------------------
// Prep: grid (NF, 8). Each (f, chunk) block builds 400 float2 LUT slots.
// ---------------------------------------------------------------------------
__global__ void prep_kernel(const float* __restrict__ cw,
                            const float* __restrict__ scale_f,
                            const float* __restrict__ rbfw,
                            const float* __restrict__ rbfc) {
    int f = blockIdx.x;
    int c = blockIdx.y;          // 0..7, 400 slots each
    int t = threadIdx.x;
    __shared__ float s_wm[NM];
    __shared__ float s_c[NM];
    __shared__ float s_val[401];
    __shared__ float sw[49];
    __shared__ float s_norm[2];

    if (t < NM) { s_wm[t] = rbfw[f*NM + t]; s_c[t] = rbfc[t]; }
    if (c == 0) {
        if (t < 49) sw[t] = cw[f*49 + t];
        if (t == 0 && f < NB) g_sums[f] = 0.f;
    }
    __syncthreads();

    int base = c * 400;
    for (int j = t; j < 401; j += 256) {
        float x = -100.f + (float)(base + j) * 0.0625f;
        float a0 = 0.f, a1 = 0.f, a2 = 0.f, a3 = 0.f;
        int m = 0;
        for (; m + 4 <= NM; m += 4) {
            float d0 = x - s_c[m+0]; a0 = fmaf(s_wm[m+0], __expf(-0.01f*d0*d0), a0);
            float d1 = x - s_c[m+1]; a1 = fmaf(s_wm[m+1], __expf(-0.01f*d1*d1), a1);
            float d2 = x - s_c[m+2]; a2 = fmaf(s_wm[m+2], __expf(-0.01f*d2*d2), a2);
            float d3 = x - s_c[m+3]; a3 = fmaf(s_wm[m+3], __expf(-0.01f*d3*d3), a3);
        }
        for (; m < NM; m++) {
            float d = x - s_c[m]; a0 = fmaf(s_wm[m], __expf(-0.01f*d*d), a0);
        }
        s_val[j] = (a0 + a1) + (a2 + a3);
    }
    if (c == 0 && t == 0) {
        float mn = 0.f;
        for (int i = 0; i < 49; i++) mn += sw[i];
        mn *= (1.f/49.f);
        float ss = 0.f;
        for (int i = 0; i < 49; i++) { float v = sw[i]-mn; ss += v*v; }
        s_norm[0] = mn;
        s_norm[1] = scale_f[f] / (sqrtf(ss) + 1e-12f);
    }
    __syncthreads();
    for (int j = t; j < 400; j += 256) {
        float v0 = s_val[j], v1 = s_val[j+1];
        g_lut2[f*LUTS + base + j] = make_float2(v0, v1 - v0);
    }
    if (c == 0 && t < 49) g_wn[f*49 + t] = (sw[t] - s_norm[0]) * s_norm[1];
}

// ---------------------------------------------------------------------------
// Main fused kernel, FFMA2 (fma.rn.f32x2) packed across the filter pair.
// One CTA = 32x32 output tile, 256 threads, 4 CTAs/SM, 24 barrier phases.
// Activation tile stored as float2(a_fA, a_fB) -> transpose loads pre-packed.
// ---------------------------------------------------------------------------
__global__ void __launch_bounds__(256, 4)
main_kernel(const float* __restrict__ input, const float* __restrict__ net_input) {
    __shared__ float  s_in[44][48];          // input halo tile (stride 48)
    __shared__ float2 s_a2[2][38][40];       // [buf][row][col] = (aA, aB)
    __shared__ float2 s_wp[24*49];           // (wA, wB) interleaved weight pairs
    __shared__ float  s_red[8];

    int t = threadIdx.x;
    int b = blockIdx.z;
    int ty0 = blockIdx.y << 5;
    int tx0 = blockIdx.x << 5;
    const float* inb = input + b*(HH*WW);

    for (int idx = t; idx < 44*44; idx += 256) {
        int iy = idx / 44, ix = idx - iy*44;
        int gy = ty0 - 6 + iy, gx = tx0 - 6 + ix;
        gy = gy < 0 ? -1-gy : (gy > 255 ? 511-gy : gy);
        gx = gx < 0 ? -1-gx : (gx > 255 ? 511-gx : gx);
        s_in[iy][ix] = inb[(gy<<8) + gx];
    }
    for (int idx = t; idx < 24*49; idx += 256) {
        int p = idx / 49, i = idx - p*49;
        s_wp[idx] = make_float2(g_wn[(2*p)*49 + i], g_wn[(2*p+1)*49 + i]);
    }

    // persistent transpose accumulator pairs: (accA_k, accB_k) summed over pairs
    u64 pacc0 = 0ull, pacc1 = 0ull, pacc2 = 0ull, pacc3 = 0ull;
    int orow = t >> 3;             // 0..31
    int ocol = (t & 7) << 2;       // 0..28

    int zr = t / 5;                // z tasks: 38 rows x 5 strips of 8
    int zg = (t - zr*5) << 3;
    bool zact = (t < 190);
    int zgr = ty0 - 3 + zr;
    int zgc0 = tx0 - 3 + zg;
    bool rowok = (zgr >= 0) && (zgr < 256);
    unsigned cmask = 0u;
    #pragma unroll
    for (int k = 0; k < 8; k++) {
        int zgc = zgc0 + k;
        if (rowok && zgc >= 0 && zgc < 256) cmask |= (1u << k);
    }

    __syncthreads();   // tiles + weight pairs ready

    for (int p = 0; p < NF/2; p++) {
        const u64* wp64 = reinterpret_cast<const u64*>(&s_wp[p*49]);
        int bsel = p & 1;
        if (zact) {
            u64 zp[8];
            #pragma unroll
            for (int k = 0; k < 8; k++) zp[k] = 0ull;
            #pragma unroll
            for (int u = 0; u < 7; u++) {
                const float* rp = &s_in[zr+u][zg];
                float4 q0 = *(const float4*)(rp);
                float4 q1 = *(const float4*)(rp+4);
                float4 q2 = *(const float4*)(rp+8);
                float2 q3 = *(const float2*)(rp+12);
                float vals[14] = {q0.x,q0.y,q0.z,q0.w, q1.x,q1.y,q1.z,q1.w,
                                  q2.x,q2.y,q2.z,q2.w, q3.x,q3.y};
                u64 sp[14];
                #pragma unroll
                for (int j = 0; j < 8; j++) sp[j] = splat2(vals[j]);
                #pragma unroll
                for (int v = 0; v < 7; v++) {
                    if (v > 0) sp[v+7] = splat2(vals[v+7]);   // sliding window
                    u64 w2 = wp64[u*7+v];
                    #pragma unroll
                    for (int k = 0; k < 8; k++)
                        zp[k] = ffma2(sp[v+k], w2, zp[k]);
                }
            }
            const float2* luta = g_lut2 + (2*p)*LUTS;
            const float2* lutb = luta + LUTS;
            #pragma unroll
            for (int k = 0; k < 8; k++) {
                float2 zz = unpack2(zp[k]);
                float tfa = fminf(fmaxf(fmaf(zz.x, 16.f, 1600.f), 0.f), 3200.f);
                int ia = min((int)tfa, 3199);
                float fra = tfa - (float)ia;
                float2 ea = __ldg(luta + ia);
                float aa = fmaf(fra, ea.y, ea.x);

                float tfb = fminf(fmaxf(fmaf(zz.y, 16.f, 1600.f), 0.f), 3200.f);
                int ib = min((int)tfb, 3199);
                float frb = tfb - (float)ib;
                float2 eb = __ldg(lutb + ib);
                float ab = fmaf(frb, eb.y, eb.x);

                if (!((cmask >> k) & 1u)) { aa = 0.f; ab = 0.f; }
                s_a2[bsel][zr][zg+k] = make_float2(aa, ab);
            }
        }
        __syncthreads();   // pair activations ready; fences buffer reuse
        #pragma unroll
        for (int uu = 0; uu < 7; uu++) {
            const ulonglong2* rp2 =
                reinterpret_cast<const ulonglong2*>(&s_a2[bsel][orow+uu][ocol]);
            u64 vA[10];
            #pragma unroll
            for (int jj = 0; jj < 5; jj++) {
                ulonglong2 q = rp2[jj];
                vA[2*jj]   = q.x;
                vA[2*jj+1] = q.y;
            }
            #pragma unroll
            for (int vv = 0; vv < 7; vv++) {
                u64 w2 = wp64[(6-uu)*7 + (6-vv)];
                pacc0 = ffma2(vA[vv+0], w2, pacc0);
                pacc1 = ffma2(vA[vv+1], w2, pacc1);
                pacc2 = ffma2(vA[vv+2], w2, pacc2);
                pacc3 = ffma2(vA[vv+3], w2, pacc3);
            }
        }
        // no second barrier: next pair writes the OTHER buffer
    }

    float2 c0 = unpack2(pacc0), c1 = unpack2(pacc1);
    float2 c2 = unpack2(pacc2), c3 = unpack2(pacc3);
    float acc0 = c0.x + c0.y;
    float acc1 = c1.x + c1.y;
    float acc2 = c2.x + c2.y;
    float acc3 = c3.x + c3.y;

    int gy = ty0 + orow;
    int gx = tx0 + ocol;
    int base = (gy<<8) + gx;
    const float* nb_ = net_input + b*(HH*WW);
    float4 iv = *(const float4*)(inb + base);
    float4 nv = *(const float4*)(nb_ + base);
    float r0 = iv.x - acc0 - nv.x;
    float r1 = iv.y - acc1 - nv.y;
    float r2 = iv.z - acc2 - nv.z;
    float r3 = iv.w - acc3 - nv.w;
    float4 rv; rv.x=r0; rv.y=r1; rv.z=r2; rv.w=r3;
    *(float4*)(g_r + b*(HH*WW) + base) = rv;
    float ls = r0*r0 + r1*r1 + r2*r2 + r3*r3;
    #pragma unroll
    for (int off = 16; off > 0; off >>= 1)
        ls += __shfl_down_sync(0xffffffffu, ls, off);
    if ((t & 31) == 0) s_red[t>>5] = ls;
    __syncthreads();
    if (t == 0) {
        float tot = 0.f;
        #pragma unroll
        for (int i = 0; i < 8; i++) tot += s_red[i];
        atomicAdd(&g_sums[b], tot);
    }
}

// ---------------------------------------------------------------------------
// Final: out = net_input + r * min(1, k/(||r||+eps)), k = exp(alpha)*stdn*256
// ---------------------------------------------------------------------------
__global__ void final_kernel(const float* __restrict__ net_input,
                             const float* __restrict__ stdn,
                             const float* __restrict__ alpha,
                             float* __restrict__ out) {
    int i4 = blockIdx.x*256 + threadIdx.x;
    if (i4 >= NPIX/4) return;
    int b = i4 >> 14;   // 16384 float4s per batch image
    float k = expf(alpha[0]) * stdn[b] * 256.f;   // sqrt(65536)=256
    float nr = sqrtf(g_sums[b]);
    float s = fminf(1.f, k / (nr + 1e-12f));
    float4 rv = ((const float4*)g_r)[i4];
    float4 nv = ((const float4*)net_input)[i4];
    float4 ov;
    ov.x = fmaf(rv.x, s, nv.x);
    ov.y = fmaf(rv.y, s, nv.y);
    ov.z = fmaf(rv.z, s, nv.z);
    ov.w = fmaf(rv.w, s, nv.w);
    ((float4*)out)[i4] = ov;
}

extern "C" void kernel_launch(void* const* d_in, const int* in_sizes, int n_in,
                              void* d_out, int out_size) {
    const float* input     = (const float*)d_in[0];
    const float* stdn      = (const float*)d_in[1];
    // d_in[2] = rbf_data (grid baked into LUT)
    const float* net_input = (const float*)d_in[3];
    const float* cw        = (const float*)d_in[4];
    const float* scale_f   = (const float*)d_in[5];
    const float* alpha     = (const float*)d_in[6];
    const float* rbfw      = (const float*)d_in[7];
    const float* rbfc      = (const float*)d_in[8];
    float* out = (float*)d_out;

    prep_kernel<<<dim3(NF, 8), 256>>>(cw, scale_f, rbfw, rbfc);
    main_kernel<<<dim3(8, 8, NB), 256>>>(input, net_input);
    final_kernel<<<(NPIX/4 + 255)/256, 256>>>(net_input, stdn, alpha, out);
}

// round 6
// speedup vs baseline: 1.4528x; 1.4528x over previous
#include <cuda_runtime.h>
#include <cuda_bf16.h>
#include <math.h>

#define NB 16
#define NF 48
#define NM 51
#define HH 256
#define WW 256
#define LUTS 3200          // float2 slots (value, slope)
#define NPIX (NB*HH*WW)

// scratch (no allocations allowed)
__device__ float  g_wn[NF*49];
__device__ float2 g_lut2[NF*LUTS];
__device__ float  g_sums[NB];
__device__ float  g_r[NPIX];

__device__ __forceinline__ __nv_bfloat162 u2b(unsigned u) {
    return *reinterpret_cast<__nv_bfloat162*>(&u);
}
__device__ __forceinline__ unsigned b2u(__nv_bfloat162 v) {
    return *reinterpret_cast<unsigned*>(&v);
}

// ---------------------------------------------------------------------------
// Prep: grid (NF, 8). Each (f, chunk) block builds 400 float2 LUT slots.
// ---------------------------------------------------------------------------
__global__ void prep_kernel(const float* __restrict__ cw,
                            const float* __restrict__ scale_f,
                            const float* __restrict__ rbfw,
                            const float* __restrict__ rbfc) {
    int f = blockIdx.x;
    int c = blockIdx.y;          // 0..7, 400 slots each
    int t = threadIdx.x;
    __shared__ float s_wm[NM];
    __shared__ float s_c[NM];
    __shared__ float s_val[401];
    __shared__ float sw[49];
    __shared__ float s_norm[2];

    if (t < NM) { s_wm[t] = rbfw[f*NM + t]; s_c[t] = rbfc[t]; }
    if (c == 0) {
        if (t < 49) sw[t] = cw[f*49 + t];
        if (t == 0 && f < NB) g_sums[f] = 0.f;
    }
    __syncthreads();

    int base = c * 400;
    for (int j = t; j < 401; j += 256) {
        float x = -100.f + (float)(base + j) * 0.0625f;
        float a0 = 0.f, a1 = 0.f, a2 = 0.f, a3 = 0.f;
        int m = 0;
        for (; m + 4 <= NM; m += 4) {
            float d0 = x - s_c[m+0]; a0 = fmaf(s_wm[m+0], __expf(-0.01f*d0*d0), a0);
            float d1 = x - s_c[m+1]; a1 = fmaf(s_wm[m+1], __expf(-0.01f*d1*d1), a1);
            float d2 = x - s_c[m+2]; a2 = fmaf(s_wm[m+2], __expf(-0.01f*d2*d2), a2);
            float d3 = x - s_c[m+3]; a3 = fmaf(s_wm[m+3], __expf(-0.01f*d3*d3), a3);
        }
        for (; m < NM; m++) {
            float d = x - s_c[m]; a0 = fmaf(s_wm[m], __expf(-0.01f*d*d), a0);
        }
        s_val[j] = (a0 + a1) + (a2 + a3);
    }
    if (c == 0 && t == 0) {
        float mn = 0.f;
        for (int i = 0; i < 49; i++) mn += sw[i];
        mn *= (1.f/49.f);
        float ss = 0.f;
        for (int i = 0; i < 49; i++) { float v = sw[i]-mn; ss += v*v; }
        s_norm[0] = mn;
        s_norm[1] = scale_f[f] / (sqrtf(ss) + 1e-12f);
    }
    __syncthreads();
    for (int j = t; j < 400; j += 256) {
        float v0 = s_val[j], v1 = s_val[j+1];
        g_lut2[f*LUTS + base + j] = make_float2(v0, v1 - v0);
    }
    if (c == 0 && t < 49) g_wn[f*49 + t] = (sw[t] - s_norm[0]) * s_norm[1];
}

// ---------------------------------------------------------------------------
// Main fused kernel: HFMA2 (bf16x2) packed across the filter pair.
// One CTA = 32x32 output tile, 256 threads, 4 CTAs/SM, 24 barrier phases.
// Input tile stored PRE-SPLATTED bf16x2(x,x); activation tile bf16x2(aA,aB).
// z accumulated in bf16x2; transpose accumulated bf16x2 per pair, folded to
// fp32 across pairs. LUT lerp stays fp32.
// ---------------------------------------------------------------------------
__global__ void __launch_bounds__(256, 4)
main_kernel(const float* __restrict__ input, const float* __restrict__ net_input) {
    __shared__ unsigned s_in[44][48];        // bf16x2 splat(x,x), stride 48
    __shared__ unsigned s_a2[2][38][40];     // bf16x2 (aA, aB), double-buffered
    __shared__ __nv_bfloat162 s_wp[24*49];   // (bf16 wA, bf16 wB) per pair
    __shared__ float s_red[8];

    int t = threadIdx.x;
    int b = blockIdx.z;
    int ty0 = blockIdx.y << 5;
    int tx0 = blockIdx.x << 5;
    const float* inb = input + b*(HH*WW);

    for (int idx = t; idx < 44*44; idx += 256) {
        int iy = idx / 44, ix = idx - iy*44;
        int gy = ty0 - 6 + iy, gx = tx0 - 6 + ix;
        gy = gy < 0 ? -1-gy : (gy > 255 ? 511-gy : gy);
        gx = gx < 0 ? -1-gx : (gx > 255 ? 511-gx : gx);
        float x = inb[(gy<<8) + gx];
        s_in[iy][ix] = b2u(__float2bfloat162_rn(x));   // splat once here
    }
    for (int idx = t; idx < 24*49; idx += 256) {
        int p = idx / 49, i = idx - p*49;
        s_wp[idx] = __floats2bfloat162_rn(g_wn[(2*p)*49 + i], g_wn[(2*p+1)*49 + i]);
    }

    // fp32 transpose accumulators (folded from bf16x2 pair-accumulators)
    float accf0 = 0.f, accf1 = 0.f, accf2 = 0.f, accf3 = 0.f;
    int orow = t >> 3;             // 0..31
    int ocol = (t & 7) << 2;       // 0..28

    int zr = t / 5;                // z tasks: 38 rows x 5 strips of 8
    int zg = (t - zr*5) << 3;
    bool zact = (t < 190);
    int zgr = ty0 - 3 + zr;
    int zgc0 = tx0 - 3 + zg;
    bool rowok = (zgr >= 0) && (zgr < 256);
    unsigned cmask = 0u;
    #pragma unroll
    for (int k = 0; k < 8; k++) {
        int zgc = zgc0 + k;
        if (rowok && zgc >= 0 && zgc < 256) cmask |= (1u << k);
    }

    __syncthreads();   // tiles + weight pairs ready

    for (int p = 0; p < NF/2; p++) {
        const __nv_bfloat162* wf = &s_wp[p*49];
        int bsel = p & 1;
        if (zact) {
            __nv_bfloat162 zp[8];
            #pragma unroll
            for (int k = 0; k < 8; k++) zp[k] = __floats2bfloat162_rn(0.f, 0.f);
            #pragma unroll
            for (int u = 0; u < 7; u++) {
                const unsigned* rp = &s_in[zr+u][zg];
                uint4 q0 = *(const uint4*)(rp);
                uint4 q1 = *(const uint4*)(rp+4);
                uint4 q2 = *(const uint4*)(rp+8);
                uint2 q3 = *(const uint2*)(rp+12);
                __nv_bfloat162 sp[14] = {
                    u2b(q0.x), u2b(q0.y), u2b(q0.z), u2b(q0.w),
                    u2b(q1.x), u2b(q1.y), u2b(q1.z), u2b(q1.w),
                    u2b(q2.x), u2b(q2.y), u2b(q2.z), u2b(q2.w),
                    u2b(q3.x), u2b(q3.y)};
                #pragma unroll
                for (int v = 0; v < 7; v++) {
                    __nv_bfloat162 w2 = wf[u*7+v];
                    #pragma unroll
                    for (int k = 0; k < 8; k++)
                        zp[k] = __hfma2(sp[v+k], w2, zp[k]);
                }
            }
            const float2* luta = g_lut2 + (2*p)*LUTS;
            const float2* lutb = luta + LUTS;
            #pragma unroll
            for (int k = 0; k < 8; k++) {
                float za = __low2float(zp[k]);
                float zb = __high2float(zp[k]);
                float tfa = fminf(fmaxf(fmaf(za, 16.f, 1600.f), 0.f), 3200.f);
                int ia = min((int)tfa, 3199);
                float fra = tfa - (float)ia;
                float2 ea = __ldg(luta + ia);
                float aa = fmaf(fra, ea.y, ea.x);

                float tfb = fminf(fmaxf(fmaf(zb, 16.f, 1600.f), 0.f), 3200.f);
                int ib = min((int)tfb, 3199);
                float frb = tfb - (float)ib;
                float2 eb = __ldg(lutb + ib);
                float ab = fmaf(frb, eb.y, eb.x);

                if (!((cmask >> k) & 1u)) { aa = 0.f; ab = 0.f; }
                s_a2[bsel][zr][zg+k] = b2u(__floats2bfloat162_rn(aa, ab));
            }
        }
        __syncthreads();   // pair activations ready; fences buffer reuse

        __nv_bfloat162 pa0 = __floats2bfloat162_rn(0.f, 0.f);
        __nv_bfloat162 pa1 = pa0, pa2 = pa0, pa3 = pa0;
        #pragma unroll
        for (int uu = 0; uu < 7; uu++) {
            const unsigned* rp = &s_a2[bsel][orow+uu][ocol];
            uint4 q0 = *(const uint4*)(rp);
            uint4 q1 = *(const uint4*)(rp+4);
            uint2 q2 = *(const uint2*)(rp+8);
            __nv_bfloat162 vals[10] = {
                u2b(q0.x), u2b(q0.y), u2b(q0.z), u2b(q0.w),
                u2b(q1.x), u2b(q1.y), u2b(q1.z), u2b(q1.w),
                u2b(q2.x), u2b(q2.y)};
            #pragma unroll
            for (int vv = 0; vv < 7; vv++) {
                __nv_bfloat162 w2 = wf[(6-uu)*7 + (6-vv)];
                pa0 = __hfma2(vals[vv+0], w2, pa0);
                pa1 = __hfma2(vals[vv+1], w2, pa1);
                pa2 = __hfma2(vals[vv+2], w2, pa2);
                pa3 = __hfma2(vals[vv+3], w2, pa3);
            }
        }
        // fold pair (lo = filter A, hi = filter B) into fp32 accumulators
        accf0 += __low2float(pa0) + __high2float(pa0);
        accf1 += __low2float(pa1) + __high2float(pa1);
        accf2 += __low2float(pa2) + __high2float(pa2);
        accf3 += __low2float(pa3) + __high2float(pa3);
        // no second barrier: next pair writes the OTHER buffer
    }

    int gy = ty0 + orow;
    int gx = tx0 + ocol;
    int base = (gy<<8) + gx;
    const float* nb_ = net_input + b*(HH*WW);
    float4 iv = *(const float4*)(inb + base);
    float4 nv = *(const float4*)(nb_ + base);
    float r0 = iv.x - accf0 - nv.x;
    float r1 = iv.y - accf1 - nv.y;
    float r2 = iv.z - accf2 - nv.z;
    float r3 = iv.w - accf3 - nv.w;
    float4 rv; rv.x=r0; rv.y=r1; rv.z=r2; rv.w=r3;
    *(float4*)(g_r + b*(HH*WW) + base) = rv;
    float ls = r0*r0 + r1*r1 + r2*r2 + r3*r3;
    #pragma unroll
    for (int off = 16; off > 0; off >>= 1)
        ls += __shfl_down_sync(0xffffffffu, ls, off);
    if ((t & 31) == 0) s_red[t>>5] = ls;
    __syncthreads();
    if (t == 0) {
        float tot = 0.f;
        #pragma unroll
        for (int i = 0; i < 8; i++) tot += s_red[i];
        atomicAdd(&g_sums[b], tot);
    }
}

// ---------------------------------------------------------------------------
// Final: out = net_input + r * min(1, k/(||r||+eps)), k = exp(alpha)*stdn*256
// ---------------------------------------------------------------------------
__global__ void final_kernel(const float* __restrict__ net_input,
                             const float* __restrict__ stdn,
                             const float* __restrict__ alpha,
                             float* __restrict__ out) {
    int i4 = blockIdx.x*256 + threadIdx.x;
    if (i4 >= NPIX/4) return;
    int b = i4 >> 14;   // 16384 float4s per batch image
    float k = expf(alpha[0]) * stdn[b] * 256.f;   // sqrt(65536)=256
    float nr = sqrtf(g_sums[b]);
    float s = fminf(1.f, k / (nr + 1e-12f));
    float4 rv = ((const float4*)g_r)[i4];
    float4 nv = ((const float4*)net_input)[i4];
    float4 ov;
    ov.x = fmaf(rv.x, s, nv.x);
    ov.y = fmaf(rv.y, s, nv.y);
    ov.z = fmaf(rv.z, s, nv.z);
    ov.w = fmaf(rv.w, s, nv.w);
    ((float4*)out)[i4] = ov;
}

extern "C" void kernel_launch(void* const* d_in, const int* in_sizes, int n_in,
                              void* d_out, int out_size) {
    const float* input     = (const float*)d_in[0];
    const float* stdn      = (const float*)d_in[1];
    // d_in[2] = rbf_data (grid baked into LUT)
    const float* net_input = (const float*)d_in[3];
    const float* cw        = (const float*)d_in[4];
    const float* scale_f   = (const float*)d_in[5];
    const float* alpha     = (const float*)d_in[6];
    const float* rbfw      = (const float*)d_in[7];
    const float* rbfc      = (const float*)d_in[8];
    float* out = (float*)d_out;

    prep_kernel<<<dim3(NF, 8), 256>>>(cw, scale_f, rbfw, rbfc);
    main_kernel<<<dim3(8, 8, NB), 256>>>(input, net_input);
    final_kernel<<<(NPIX/4 + 255)/256, 256>>>(net_input, stdn, alpha, out);
}

// round 7
// speedup vs baseline: 1.8023x; 1.2406x over previous
#include <cuda_runtime.h>
#include <cuda_bf16.h>
#include <math.h>

#define NB 16
#define NF 48
#define NM 51
#define HH 256
#define WW 256
#define LUTS 3200          // float2 slots (value, slope)
#define NPIX (NB*HH*WW)

// scratch (no allocations allowed)
__device__ float  g_wn[NF*49];
__device__ float2 g_lut2[NF*LUTS];
__device__ float  g_sums[NB];
__device__ float  g_r[NPIX];

__device__ __forceinline__ __nv_bfloat162 u2b(unsigned u) {
    return *reinterpret_cast<__nv_bfloat162*>(&u);
}
__device__ __forceinline__ unsigned b2u(__nv_bfloat162 v) {
    return *reinterpret_cast<unsigned*>(&v);
}

// ---------------------------------------------------------------------------
// Prep: grid (NF, 8). Each (f, chunk) block builds 400 float2 LUT slots.
// ---------------------------------------------------------------------------
__global__ void prep_kernel(const float* __restrict__ cw,
                            const float* __restrict__ scale_f,
                            const float* __restrict__ rbfw,
                            const float* __restrict__ rbfc) {
    int f = blockIdx.x;
    int c = blockIdx.y;          // 0..7, 400 slots each
    int t = threadIdx.x;
    __shared__ float s_wm[NM];
    __shared__ float s_c[NM];
    __shared__ float s_val[401];
    __shared__ float sw[49];
    __shared__ float s_norm[2];

    if (t < NM) { s_wm[t] = rbfw[f*NM + t]; s_c[t] = rbfc[t]; }
    if (c == 0) {
        if (t < 49) sw[t] = cw[f*49 + t];
        if (t == 0 && f < NB) g_sums[f] = 0.f;
    }
    __syncthreads();

    int base = c * 400;
    for (int j = t; j < 401; j += 256) {
        float x = -100.f + (float)(base + j) * 0.0625f;
        float a0 = 0.f, a1 = 0.f, a2 = 0.f, a3 = 0.f;
        int m = 0;
        for (; m + 4 <= NM; m += 4) {
            float d0 = x - s_c[m+0]; a0 = fmaf(s_wm[m+0], __expf(-0.01f*d0*d0), a0);
            float d1 = x - s_c[m+1]; a1 = fmaf(s_wm[m+1], __expf(-0.01f*d1*d1), a1);
            float d2 = x - s_c[m+2]; a2 = fmaf(s_wm[m+2], __expf(-0.01f*d2*d2), a2);
            float d3 = x - s_c[m+3]; a3 = fmaf(s_wm[m+3], __expf(-0.01f*d3*d3), a3);
        }
        for (; m < NM; m++) {
            float d = x - s_c[m]; a0 = fmaf(s_wm[m], __expf(-0.01f*d*d), a0);
        }
        s_val[j] = (a0 + a1) + (a2 + a3);
    }
    if (c == 0 && t == 0) {
        float mn = 0.f;
        for (int i = 0; i < 49; i++) mn += sw[i];
        mn *= (1.f/49.f);
        float ss = 0.f;
        for (int i = 0; i < 49; i++) { float v = sw[i]-mn; ss += v*v; }
        s_norm[0] = mn;
        s_norm[1] = scale_f[f] / (sqrtf(ss) + 1e-12f);
    }
    __syncthreads();
    for (int j = t; j < 400; j += 256) {
        float v0 = s_val[j], v1 = s_val[j+1];
        g_lut2[f*LUTS + base + j] = make_float2(v0, v1 - v0);
    }
    if (c == 0 && t < 49) g_wn[f*49 + t] = (sw[t] - s_norm[0]) * s_norm[1];
}

// ---------------------------------------------------------------------------
// Main fused kernel: HFMA2 (bf16x2), FOUR filters (2 bf16x2 pairs) per phase.
// One CTA = 32x32 output tile, 256 threads, 4 CTAs/SM.
// 12 phases, 2 barriers each. z-phase input splats shared across all 4 filters.
// z accumulated in bf16x2; transpose accumulated bf16x2 per pair, folded to
// fp32 across pairs. LUT lerp stays fp32.
// ---------------------------------------------------------------------------
__global__ void __launch_bounds__(256, 4)
main_kernel(const float* __restrict__ input, const float* __restrict__ net_input) {
    __shared__ unsigned s_in[44][48];        // bf16x2 splat(x,x), stride 48
    __shared__ unsigned s_a2[2][38][40];     // bf16x2 (aA, aB), one per pair
    __shared__ __nv_bfloat162 s_wp[24*49];   // (bf16 wA, bf16 wB) per pair
    __shared__ float s_red[8];

    int t = threadIdx.x;
    int b = blockIdx.z;
    int ty0 = blockIdx.y << 5;
    int tx0 = blockIdx.x << 5;
    const float* inb = input + b*(HH*WW);

    for (int idx = t; idx < 44*44; idx += 256) {
        int iy = idx / 44, ix = idx - iy*44;
        int gy = ty0 - 6 + iy, gx = tx0 - 6 + ix;
        gy = gy < 0 ? -1-gy : (gy > 255 ? 511-gy : gy);
        gx = gx < 0 ? -1-gx : (gx > 255 ? 511-gx : gx);
        float x = inb[(gy<<8) + gx];
        s_in[iy][ix] = b2u(__float2bfloat162_rn(x));   // splat once here
    }
    for (int idx = t; idx < 24*49; idx += 256) {
        int p = idx / 49, i = idx - p*49;
        s_wp[idx] = __floats2bfloat162_rn(g_wn[(2*p)*49 + i], g_wn[(2*p+1)*49 + i]);
    }

    // fp32 transpose accumulators (folded from bf16x2 pair-accumulators)
    float accf0 = 0.f, accf1 = 0.f, accf2 = 0.f, accf3 = 0.f;
    int orow = t >> 3;             // 0..31
    int ocol = (t & 7) << 2;       // 0..28

    int zr = t / 5;                // z tasks: 38 rows x 5 strips of 8
    int zg = (t - zr*5) << 3;
    bool zact = (t < 190);
    int zgr = ty0 - 3 + zr;
    int zgc0 = tx0 - 3 + zg;
    bool rowok = (zgr >= 0) && (zgr < 256);
    unsigned cmask = 0u;
    #pragma unroll
    for (int k = 0; k < 8; k++) {
        int zgc = zgc0 + k;
        if (rowok && zgc >= 0 && zgc < 256) cmask |= (1u << k);
    }

    __syncthreads();   // tiles + weight pairs ready

    for (int ph = 0; ph < NF/4; ph++) {
        const __nv_bfloat162* wfA = &s_wp[(2*ph)*49];      // pair A (filters 4ph,4ph+1)
        const __nv_bfloat162* wfB = wfA + 49;              // pair B (filters 4ph+2,4ph+3)
        if (zact) {
            __nv_bfloat162 zpA[8], zpB[8];
            #pragma unroll
            for (int k = 0; k < 8; k++) {
                zpA[k] = __floats2bfloat162_rn(0.f, 0.f);
                zpB[k] = __floats2bfloat162_rn(0.f, 0.f);
            }
            #pragma unroll
            for (int u = 0; u < 7; u++) {
                const unsigned* rp = &s_in[zr+u][zg];
                uint4 q0 = *(const uint4*)(rp);
                uint4 q1 = *(const uint4*)(rp+4);
                uint4 q2 = *(const uint4*)(rp+8);
                uint2 q3 = *(const uint2*)(rp+12);
                __nv_bfloat162 sp[14] = {
                    u2b(q0.x), u2b(q0.y), u2b(q0.z), u2b(q0.w),
                    u2b(q1.x), u2b(q1.y), u2b(q1.z), u2b(q1.w),
                    u2b(q2.x), u2b(q2.y), u2b(q2.z), u2b(q2.w),
                    u2b(q3.x), u2b(q3.y)};
                #pragma unroll
                for (int v = 0; v < 7; v++) {
                    __nv_bfloat162 wA = wfA[u*7+v];
                    __nv_bfloat162 wB = wfB[u*7+v];
                    #pragma unroll
                    for (int k = 0; k < 8; k++) {
                        zpA[k] = __hfma2(sp[v+k], wA, zpA[k]);
                        zpB[k] = __hfma2(sp[v+k], wB, zpB[k]);
                    }
                }
            }
            // lerp both pairs (4 filters), batched LDGs
            #pragma unroll
            for (int pp = 0; pp < 2; pp++) {
                const float2* luta = g_lut2 + (4*ph + 2*pp)*LUTS;
                const float2* lutb = luta + LUTS;
                __nv_bfloat162* zp = pp ? zpB : zpA;
                #pragma unroll
                for (int k = 0; k < 8; k++) {
                    float za = __low2float(zp[k]);
                    float zb = __high2float(zp[k]);
                    float tfa = fminf(fmaxf(fmaf(za, 16.f, 1600.f), 0.f), 3200.f);
                    int ia = min((int)tfa, 3199);
                    float fra = tfa - (float)ia;
                    float2 ea = __ldg(luta + ia);
                    float aa = fmaf(fra, ea.y, ea.x);

                    float tfb = fminf(fmaxf(fmaf(zb, 16.f, 1600.f), 0.f), 3200.f);
                    int ib = min((int)tfb, 3199);
                    float frb = tfb - (float)ib;
                    float2 eb = __ldg(lutb + ib);
                    float ab = fmaf(frb, eb.y, eb.x);

                    if (!((cmask >> k) & 1u)) { aa = 0.f; ab = 0.f; }
                    s_a2[pp][zr][zg+k] = b2u(__floats2bfloat162_rn(aa, ab));
                }
            }
        }
        __syncthreads();   // both pair-activation tiles ready
        #pragma unroll
        for (int pp = 0; pp < 2; pp++) {
            const __nv_bfloat162* wf = pp ? wfB : wfA;
            __nv_bfloat162 pa0 = __floats2bfloat162_rn(0.f, 0.f);
            __nv_bfloat162 pa1 = pa0, pa2 = pa0, pa3 = pa0;
            #pragma unroll
            for (int uu = 0; uu < 7; uu++) {
                const unsigned* rp = &s_a2[pp][orow+uu][ocol];
                uint4 q0 = *(const uint4*)(rp);
                uint4 q1 = *(const uint4*)(rp+4);
                uint2 q2 = *(const uint2*)(rp+8);
                __nv_bfloat162 vals[10] = {
                    u2b(q0.x), u2b(q0.y), u2b(q0.z), u2b(q0.w),
                    u2b(q1.x), u2b(q1.y), u2b(q1.z), u2b(q1.w),
                    u2b(q2.x), u2b(q2.y)};
                #pragma unroll
                for (int vv = 0; vv < 7; vv++) {
                    __nv_bfloat162 w2 = wf[(6-uu)*7 + (6-vv)];
                    pa0 = __hfma2(vals[vv+0], w2, pa0);
                    pa1 = __hfma2(vals[vv+1], w2, pa1);
                    pa2 = __hfma2(vals[vv+2], w2, pa2);
                    pa3 = __hfma2(vals[vv+3], w2, pa3);
                }
            }
            accf0 += __low2float(pa0) + __high2float(pa0);
            accf1 += __low2float(pa1) + __high2float(pa1);
            accf2 += __low2float(pa2) + __high2float(pa2);
            accf3 += __low2float(pa3) + __high2float(pa3);
        }
        __syncthreads();   // transpose reads done before next phase overwrites
    }

    int gy = ty0 + orow;
    int gx = tx0 + ocol;
    int base = (gy<<8) + gx;
    const float* nb_ = net_input + b*(HH*WW);
    float4 iv = *(const float4*)(inb + base);
    float4 nv = *(const float4*)(nb_ + base);
    float r0 = iv.x - accf0 - nv.x;
    float r1 = iv.y - accf1 - nv.y;
    float r2 = iv.z - accf2 - nv.z;
    float r3 = iv.w - accf3 - nv.w;
    float4 rv; rv.x=r0; rv.y=r1; rv.z=r2; rv.w=r3;
    *(float4*)(g_r + b*(HH*WW) + base) = rv;
    float ls = r0*r0 + r1*r1 + r2*r2 + r3*r3;
    #pragma unroll
    for (int off = 16; off > 0; off >>= 1)
        ls += __shfl_down_sync(0xffffffffu, ls, off);
    if ((t & 31) == 0) s_red[t>>5] = ls;
    __syncthreads();
    if (t == 0) {
        float tot = 0.f;
        #pragma unroll
        for (int i = 0; i < 8; i++) tot += s_red[i];
        atomicAdd(&g_sums[b], tot);
    }
}

// ---------------------------------------------------------------------------
// Final: out = net_input + r * min(1, k/(||r||+eps)), k = exp(alpha)*stdn*256
// ---------------------------------------------------------------------------
__global__ void final_kernel(const float* __restrict__ net_input,
                             const float* __restrict__ stdn,
                             const float* __restrict__ alpha,
                             float* __restrict__ out) {
    int i4 = blockIdx.x*256 + threadIdx.x;
    if (i4 >= NPIX/4) return;
    int b = i4 >> 14;   // 16384 float4s per batch image
    float k = expf(alpha[0]) * stdn[b] * 256.f;   // sqrt(65536)=256
    float nr = sqrtf(g_sums[b]);
    float s = fminf(1.f, k / (nr + 1e-12f));
    float4 rv = ((const float4*)g_r)[i4];
    float4 nv = ((const float4*)net_input)[i4];
    float4 ov;
    ov.x = fmaf(rv.x, s, nv.x);
    ov.y = fmaf(rv.y, s, nv.y);
    ov.z = fmaf(rv.z, s, nv.z);
    ov.w = fmaf(rv.w, s, nv.w);
    ((float4*)out)[i4] = ov;
}

extern "C" void kernel_launch(void* const* d_in, const int* in_sizes, int n_in,
                              void* d_out, int out_size) {
    const float* input     = (const float*)d_in[0];
    const float* stdn      = (const float*)d_in[1];
    // d_in[2] = rbf_data (grid baked into LUT)
    const float* net_input = (const float*)d_in[3];
    const float* cw        = (const float*)d_in[4];
    const float* scale_f   = (const float*)d_in[5];
    const float* alpha     = (const float*)d_in[6];
    const float* rbfw      = (const float*)d_in[7];
    const float* rbfc      = (const float*)d_in[8];
    float* out = (float*)d_out;

    prep_kernel<<<dim3(NF, 8), 256>>>(cw, scale_f, rbfw, rbfc);
    main_kernel<<<dim3(8, 8, NB), 256>>>(input, net_input);
    final_kernel<<<(NPIX/4 + 255)/256, 256>>>(net_input, stdn, alpha, out);
}